// round 13
// baseline (speedup 1.0000x reference)
#include <cuda_runtime.h>
#include <cuda_bf16.h>
#include <cstdint>
#include <cstddef>

// LSTM: B=64, T=512, D=512, H=512, fp32.
// Phase 0: interleave U gates -> g_U4[k*512+h] = (Uc,Ui,Uf,Uo)[k][h]
// Phase 1: P[t][b][g*512+h] = x @ W_g + b_g  (SGEMM, f32x2 FFMA, 2 CTA/SM)
// Phase 2: ONE persistent kernel, 128 CTAs x 512 threads, U in smem.
//          Release/acquire inter-CTA barrier (no threadfence), P prefetched
//          one step ahead so its latency hides behind the barrier.

typedef unsigned long long ull;

#define B_ 64
#define T_ 512
#define D_ 512
#define H_ 512

// ---------------- device scratch (static: no allocation APIs) ----------------
__device__ float      g_P[(size_t)T_ * B_ * 2048];   // 256 MB preactivations
__device__ ulonglong2 g_U4[(size_t)D_ * H_];         // 4 MB gate-interleaved U
__device__ float      g_h2[2][(size_t)H_ * B_];      // ping-pong h, layout [h][b]
__device__ unsigned   g_cnt[4 * 32];                  // per-bg barrier counters

// ---------------- f32x2 helpers ----------------
__device__ __forceinline__ void ffma2(ull& d, ull a, ull b) {
    asm("fma.rn.f32x2 %0, %1, %2, %0;" : "+l"(d) : "l"(a), "l"(b));
}
__device__ __forceinline__ ull pack2(float v) {
    ull r; asm("mov.b64 %0, {%1, %1};" : "=l"(r) : "f"(v)); return r;
}
__device__ __forceinline__ float2 up2(ull v) {
    float2 r; asm("mov.b64 {%0, %1}, %2;" : "=f"(r.x), "=f"(r.y) : "l"(v)); return r;
}

// ---------------- phase 0: build interleaved U + reset state ----------------
__global__ void build_u4(const float* __restrict__ Uc, const float* __restrict__ Ui,
                         const float* __restrict__ Uf, const float* __restrict__ Uo) {
    int i = blockIdx.x * 256 + threadIdx.x;   // i = k*512 + h
    float4 v = make_float4(Uc[i], Ui[i], Uf[i], Uo[i]);
    ((float4*)g_U4)[i] = v;
}

__global__ void zero_init() {
    int i = blockIdx.x * 256 + threadIdx.x;   // 128*256 = 32768 = H_*B_
    g_h2[0][i] = 0.f;
    if (i < 4 * 32) g_cnt[i] = 0u;
}

// ---------------- phase 1: SGEMM for preactivations ----------------
#define BM 128
#define BN 128
#define BK 8

__global__ void __launch_bounds__(256, 2)
gemm_pre(const float* __restrict__ A,
         const float* __restrict__ Wc, const float* __restrict__ Wi,
         const float* __restrict__ Wf, const float* __restrict__ Wo,
         const float* __restrict__ bc, const float* __restrict__ bi,
         const float* __restrict__ bf, const float* __restrict__ bo) {
    __shared__ __align__(16) float As[BK][BM];
    __shared__ __align__(16) float Bs[BK][BN];

    const int tid   = threadIdx.x;
    const int ntile = blockIdx.x;              // 0..15
    const int m0    = blockIdx.y * BM;
    const int gate  = ntile >> 2;
    const int hbase = (ntile & 3) * BN;
    const float* W    = (gate == 0) ? Wc : (gate == 1) ? Wi : (gate == 2) ? Wf : Wo;
    const float* bias = (gate == 0) ? bc : (gate == 1) ? bi : (gate == 2) ? bf : bo;

    const int a_row = tid >> 1, a_col = (tid & 1) * 4;
    const int b_row = tid >> 5, b_col = (tid & 31) * 4;
    const int tx = tid & 15, ty = tid >> 4;

    ull acc[4][8];
#pragma unroll
    for (int i = 0; i < 4; i++)
#pragma unroll
        for (int j = 0; j < 8; j++) acc[i][j] = 0ull;

    const float* Abase = A + (size_t)(m0 + a_row) * D_ + a_col;
    const float* Wbase = W + (size_t)b_row * H_ + hbase + b_col;

    for (int k0 = 0; k0 < D_; k0 += BK) {
        float4 av = *(const float4*)(Abase + k0);
        As[a_col + 0][a_row] = av.x;
        As[a_col + 1][a_row] = av.y;
        As[a_col + 2][a_row] = av.z;
        As[a_col + 3][a_row] = av.w;
        *(float4*)&Bs[b_row][b_col] = *(const float4*)(Wbase + (size_t)k0 * H_);
        __syncthreads();

#pragma unroll
        for (int kk = 0; kk < BK; kk++) {
            const ull* a64 = (const ull*)&As[kk][0];
            ull aP[4];
            aP[0] = a64[ty * 2];
            aP[1] = a64[ty * 2 + 1];
            aP[2] = a64[ty * 2 + 32];
            aP[3] = a64[ty * 2 + 33];
            float4 bv0 = *(const float4*)&Bs[kk][tx * 4];
            float4 bv1 = *(const float4*)&Bs[kk][tx * 4 + 64];
            ull bp[8];
            bp[0] = pack2(bv0.x); bp[1] = pack2(bv0.y);
            bp[2] = pack2(bv0.z); bp[3] = pack2(bv0.w);
            bp[4] = pack2(bv1.x); bp[5] = pack2(bv1.y);
            bp[6] = pack2(bv1.z); bp[7] = pack2(bv1.w);
#pragma unroll
            for (int ip = 0; ip < 4; ip++)
#pragma unroll
                for (int j = 0; j < 8; j++) ffma2(acc[ip][j], aP[ip], bp[j]);
        }
        __syncthreads();
    }

    float bias0[4], bias1[4];
#pragma unroll
    for (int j = 0; j < 4; j++) {
        bias0[j] = __ldg(&bias[hbase + tx * 4 + j]);
        bias1[j] = __ldg(&bias[hbase + 64 + tx * 4 + j]);
    }
#pragma unroll
    for (int ip = 0; ip < 4; ip++) {
        const int m_l = (ip < 2) ? (ty * 4 + ip * 2) : (64 + ty * 4 + (ip - 2) * 2);
        float2 c0 = up2(acc[ip][0]), c1 = up2(acc[ip][1]);
        float2 c2 = up2(acc[ip][2]), c3 = up2(acc[ip][3]);
        float2 c4 = up2(acc[ip][4]), c5 = up2(acc[ip][5]);
        float2 c6 = up2(acc[ip][6]), c7 = up2(acc[ip][7]);
#pragma unroll
        for (int lane = 0; lane < 2; lane++) {
            const int row = m0 + m_l + lane;        // row = b*512 + t
            const int b = row >> 9, t = row & 511;
            float* dst = g_P + ((size_t)(t * B_ + b)) * 2048 + (size_t)gate * 512 + hbase;
            float4 v0, v1;
            if (lane == 0) {
                v0 = make_float4(c0.x + bias0[0], c1.x + bias0[1], c2.x + bias0[2], c3.x + bias0[3]);
                v1 = make_float4(c4.x + bias1[0], c5.x + bias1[1], c6.x + bias1[2], c7.x + bias1[3]);
            } else {
                v0 = make_float4(c0.y + bias0[0], c1.y + bias0[1], c2.y + bias0[2], c3.y + bias0[3]);
                v1 = make_float4(c4.y + bias1[0], c5.y + bias1[1], c6.y + bias1[2], c7.y + bias1[3]);
            }
            *(float4*)(dst + tx * 4)      = v0;
            *(float4*)(dst + 64 + tx * 4) = v1;
        }
    }
}

// ---------------- phase 2: persistent recurrence ----------------
// 128 CTAs = 4 bg x 32 hg. CTA tile: 16 b x 16 h. 512 threads (16 warps).
// Thread: h_l = tid&15, bh = (tid>>4)&1 (8-b half), ks = tid>>5 (32-k slice).
// smem: sU [512k][16h] ulonglong2 (128 KB, staged once)
//       alias region (69632 B): sHd [512k][32] dup pairs / sRed [16][16][34]

#define SU_BYTES    (D_ * 16 * 16)             // 131072
#define ALIAS_BYTES (16 * 16 * 34 * 8)         // 69632 (>= SHD 65536)
#define SMEM_REC    (SU_BYTES + ALIAS_BYTES)   // 200704

__global__ void __launch_bounds__(512, 1) lstm_rec(float* __restrict__ out) {
    extern __shared__ __align__(16) char smem[];
    ulonglong2* sU   = (ulonglong2*)smem;                // [k*16 + h_l]
    float*      sHd  = (float*)(smem + SU_BYTES);        // [k*32] dup pairs
    ull*        sRed = (ull*)(smem + SU_BYTES);          // aliases sHd

    const int tid = threadIdx.x;
    const int hg = blockIdx.x & 31, bg = blockIdx.x >> 5;
    const int h0 = hg * 16, b0 = bg * 16;
    const int h_l = tid & 15;
    const int bh  = (tid >> 4) & 1;
    const int ks  = tid >> 5;                    // 0..15, warp-uniform
    const int kbase = ks * 32;
    const int eb = tid >> 4;                     // epilogue b (valid tid<256)
    unsigned* bar = &g_cnt[bg * 32];

    // stage U tile into smem once: 8192 ulonglong2, 16 per thread (coalesced)
#pragma unroll
    for (int j = 0; j < 16; j++) {
        int idx = tid + j * 512;                 // idx = k*16 + hh
        int k = idx >> 4, hh = idx & 15;
        sU[idx] = g_U4[(size_t)k * H_ + h0 + hh];
    }

    float c_reg = 0.f;
    const float* Pbase = g_P + (size_t)(b0 + (eb & 15)) * 2048 + h0 + h_l;

    // pre-load P[0] (later steps are prefetched from inside the epilogue)
    float p0 = 0.f, p1 = 0.f, p2 = 0.f, p3 = 0.f;
    if (tid < 256) {
        p0 = __ldg(Pbase);
        p1 = __ldg(Pbase + 512);
        p2 = __ldg(Pbase + 1024);
        p3 = __ldg(Pbase + 1536);
    }

    __syncthreads();

    for (int t = 0; t < T_; t++) {
        // stage h_{t-1}: global [h][b] -> smem duplicated pairs {h,h}
        {
            const float* hb = g_h2[t & 1];
            float4 v[4];
#pragma unroll
            for (int j = 0; j < 4; j++) {
                int task = tid + j * 512;
                int k = task >> 2, q = task & 3;
                v[j] = *(const float4*)(hb + (size_t)k * B_ + b0 + q * 4);
            }
#pragma unroll
            for (int j = 0; j < 4; j++) {
                int task = tid + j * 512;
                int k = task >> 2, q = task & 3;
                *(float4*)&sHd[k * 32 + q * 8] =
                    make_float4(v[j].x, v[j].x, v[j].y, v[j].y);
                *(float4*)&sHd[k * 32 + q * 8 + 4] =
                    make_float4(v[j].z, v[j].z, v[j].w, v[j].w);
            }
        }
        __syncthreads();

        // partial gate sums: 8 b x 32 k per thread, U streamed from smem
        ull acc[8][2];
#pragma unroll
        for (int j = 0; j < 8; j++) { acc[j][0] = 0ull; acc[j][1] = 0ull; }
        {
            const ulonglong2* Up = sU + kbase * 16 + h_l;
            const ulonglong2* Hp = (const ulonglong2*)sHd + kbase * 8 + bh * 4;
#pragma unroll 4
            for (int i = 0; i < 32; i++) {
                ulonglong2 u = Up[i * 16];          // (Uc,Ui | Uf,Uo)
                ulonglong2 hp0 = Hp[i * 8];         // {h0 dup, h1 dup}
                ulonglong2 hp1 = Hp[i * 8 + 1];
                ulonglong2 hp2 = Hp[i * 8 + 2];
                ulonglong2 hp3 = Hp[i * 8 + 3];
                ffma2(acc[0][0], hp0.x, u.x); ffma2(acc[0][1], hp0.x, u.y);
                ffma2(acc[1][0], hp0.y, u.x); ffma2(acc[1][1], hp0.y, u.y);
                ffma2(acc[2][0], hp1.x, u.x); ffma2(acc[2][1], hp1.x, u.y);
                ffma2(acc[3][0], hp1.y, u.x); ffma2(acc[3][1], hp1.y, u.y);
                ffma2(acc[4][0], hp2.x, u.x); ffma2(acc[4][1], hp2.x, u.y);
                ffma2(acc[5][0], hp2.y, u.x); ffma2(acc[5][1], hp2.y, u.y);
                ffma2(acc[6][0], hp3.x, u.x); ffma2(acc[6][1], hp3.x, u.y);
                ffma2(acc[7][0], hp3.y, u.x); ffma2(acc[7][1], hp3.y, u.y);
            }
        }
        __syncthreads();   // all reads of sHd done; safe to overwrite via sRed

        // dump partials (16 ull contiguous, 16B-aligned)
        {
            ulonglong2* rb = (ulonglong2*)(sRed + (ks * 16 + h_l) * 34 + bh * 16);
#pragma unroll
            for (int j = 0; j < 8; j++) {
                ulonglong2 v; v.x = acc[j][0]; v.y = acc[j][1];
                rb[j] = v;
            }
        }
        __syncthreads();

        // epilogue: 256 threads own (b = eb, h = h_l)
        if (tid < 256) {
            float pc = p0, pi = p1, pf = p2, po = p3;

            // prefetch next step's P NOW -> latency hides behind barrier
            if (t + 1 < T_) {
                const float* Pn = Pbase + (size_t)(t + 1) * B_ * 2048;
                p0 = __ldg(Pn);
                p1 = __ldg(Pn + 512);
                p2 = __ldg(Pn + 1024);
                p3 = __ldg(Pn + 1536);
            }

#pragma unroll
            for (int kk = 0; kk < 16; kk++) {
                ulonglong2 rr = *(const ulonglong2*)(sRed + (kk * 16 + h_l) * 34 + eb * 2);
                float2 v0 = up2(rr.x);
                float2 v1 = up2(rr.y);
                pc += v0.x; pi += v0.y; pf += v1.x; po += v1.y;
            }
            float a  = tanhf(pc);
            float ig = 1.f / (1.f + __expf(-pi));
            float fg = 1.f / (1.f + __expf(-pf));
            float og = 1.f / (1.f + __expf(-po));
            c_reg = ig * a + fg * c_reg;
            float hn = og * tanhf(c_reg);

            g_h2[(t + 1) & 1][(size_t)(h0 + h_l) * B_ + b0 + eb] = hn;
            out[((size_t)(b0 + eb) * T_ + t) * H_ + h0 + h_l] = hn;
        }

        // inter-CTA barrier (release/acquire; bar.sync provides CTA-wide HB)
        if (t < T_ - 1) {
            __syncthreads();
            if (tid == 0) {
                asm volatile("red.release.gpu.global.add.u32 [%0], 1;"
                             :: "l"(bar) : "memory");
                unsigned v, target = 32u * (unsigned)(t + 1);
                do {
                    asm volatile("ld.acquire.gpu.global.u32 %0, [%1];"
                                 : "=r"(v) : "l"(bar) : "memory");
                } while (v < target);
            }
            __syncthreads();
        }
    }
}

// ---------------- launch ----------------
extern "C" void kernel_launch(void* const* d_in, const int* in_sizes, int n_in,
                              void* d_out, int out_size) {
    const float* x  = (const float*)d_in[0];
    const float* Wc = (const float*)d_in[1];
    const float* Wi = (const float*)d_in[2];
    const float* Wf = (const float*)d_in[3];
    const float* Wo = (const float*)d_in[4];
    const float* Uc = (const float*)d_in[5];
    const float* Ui = (const float*)d_in[6];
    const float* Uf = (const float*)d_in[7];
    const float* Uo = (const float*)d_in[8];
    const float* bc = (const float*)d_in[9];
    const float* bi = (const float*)d_in[10];
    const float* bf = (const float*)d_in[11];
    const float* bo = (const float*)d_in[12];
    float* out = (float*)d_out;

    static bool attr_set = false;
    if (!attr_set) {
        cudaFuncSetAttribute(lstm_rec, cudaFuncAttributeMaxDynamicSharedMemorySize, SMEM_REC);
        attr_set = true;
    }

    zero_init<<<128, 256>>>();
    build_u4<<<(D_ * H_) / 256, 256>>>(Uc, Ui, Uf, Uo);

    dim3 ggrid(2048 / BN, (B_ * T_) / BM);   // (16, 256)
    gemm_pre<<<ggrid, 256>>>(x, Wc, Wi, Wf, Wo, bc, bi, bf, bo);

    lstm_rec<<<128, 512, SMEM_REC>>>(out);
}

// round 14
// speedup vs baseline: 1.2380x; 1.2380x over previous
#include <cuda_runtime.h>
#include <cuda_bf16.h>
#include <cstdint>
#include <cstddef>

// LSTM: B=64, T=512, D=512, H=512, fp32.
// Phase 0: interleave U gates -> g_U4[k*512+h] = (Uc,Ui,Uf,Uo)[k][h]
// Phase 1: P[t][b][g*512+h] = x @ W_g + b_g  (SGEMM, f32x2 FFMA, 2 CTA/SM)
// Phase 2: persistent recurrence (R9 core: 256 thr, U register-resident),
//          release/acquire inter-CTA barrier, P[t+1] prefetched in epilogue.

typedef unsigned long long ull;

#define B_ 64
#define T_ 512
#define D_ 512
#define H_ 512

// ---------------- device scratch (static: no allocation APIs) ----------------
__device__ float      g_P[(size_t)T_ * B_ * 2048];   // 256 MB preactivations
__device__ ulonglong2 g_U4[(size_t)D_ * H_];         // 4 MB gate-interleaved U
__device__ float      g_h2[2][(size_t)H_ * B_];      // ping-pong h, layout [h][b]
__device__ unsigned   g_cnt[4 * 32];                  // per-bg barrier counters

// ---------------- f32x2 helpers ----------------
__device__ __forceinline__ void ffma2(ull& d, ull a, ull b) {
    asm("fma.rn.f32x2 %0, %1, %2, %0;" : "+l"(d) : "l"(a), "l"(b));
}
__device__ __forceinline__ ull pack2(float v) {
    ull r; asm("mov.b64 %0, {%1, %1};" : "=l"(r) : "f"(v)); return r;
}
__device__ __forceinline__ float2 up2(ull v) {
    float2 r; asm("mov.b64 {%0, %1}, %2;" : "=f"(r.x), "=f"(r.y) : "l"(v)); return r;
}

// ---------------- phase 0: build interleaved U + reset state ----------------
__global__ void build_u4(const float* __restrict__ Uc, const float* __restrict__ Ui,
                         const float* __restrict__ Uf, const float* __restrict__ Uo) {
    int i = blockIdx.x * 256 + threadIdx.x;   // i = k*512 + h
    float4 v = make_float4(Uc[i], Ui[i], Uf[i], Uo[i]);
    ((float4*)g_U4)[i] = v;
}

__global__ void zero_init() {
    int i = blockIdx.x * 256 + threadIdx.x;   // 128*256 = 32768 = H_*B_
    g_h2[0][i] = 0.f;
    if (i < 4 * 32) g_cnt[i] = 0u;
}

// ---------------- phase 1: SGEMM for preactivations (2 CTA/SM) ----------------
#define BM 128
#define BN 128
#define BK 8

__global__ void __launch_bounds__(256, 2)
gemm_pre(const float* __restrict__ A,
         const float* __restrict__ Wc, const float* __restrict__ Wi,
         const float* __restrict__ Wf, const float* __restrict__ Wo,
         const float* __restrict__ bc, const float* __restrict__ bi,
         const float* __restrict__ bf, const float* __restrict__ bo) {
    __shared__ __align__(16) float As[BK][BM];
    __shared__ __align__(16) float Bs[BK][BN];

    const int tid   = threadIdx.x;
    const int ntile = blockIdx.x;              // 0..15
    const int m0    = blockIdx.y * BM;
    const int gate  = ntile >> 2;
    const int hbase = (ntile & 3) * BN;
    const float* W    = (gate == 0) ? Wc : (gate == 1) ? Wi : (gate == 2) ? Wf : Wo;
    const float* bias = (gate == 0) ? bc : (gate == 1) ? bi : (gate == 2) ? bf : bo;

    const int a_row = tid >> 1, a_col = (tid & 1) * 4;
    const int b_row = tid >> 5, b_col = (tid & 31) * 4;
    const int tx = tid & 15, ty = tid >> 4;

    ull acc[4][8];
#pragma unroll
    for (int i = 0; i < 4; i++)
#pragma unroll
        for (int j = 0; j < 8; j++) acc[i][j] = 0ull;

    const float* Abase = A + (size_t)(m0 + a_row) * D_ + a_col;
    const float* Wbase = W + (size_t)b_row * H_ + hbase + b_col;

    for (int k0 = 0; k0 < D_; k0 += BK) {
        float4 av = *(const float4*)(Abase + k0);
        As[a_col + 0][a_row] = av.x;
        As[a_col + 1][a_row] = av.y;
        As[a_col + 2][a_row] = av.z;
        As[a_col + 3][a_row] = av.w;
        *(float4*)&Bs[b_row][b_col] = *(const float4*)(Wbase + (size_t)k0 * H_);
        __syncthreads();

#pragma unroll
        for (int kk = 0; kk < BK; kk++) {
            const ull* a64 = (const ull*)&As[kk][0];
            ull aP[4];
            aP[0] = a64[ty * 2];
            aP[1] = a64[ty * 2 + 1];
            aP[2] = a64[ty * 2 + 32];
            aP[3] = a64[ty * 2 + 33];
            float4 bv0 = *(const float4*)&Bs[kk][tx * 4];
            float4 bv1 = *(const float4*)&Bs[kk][tx * 4 + 64];
            ull bp[8];
            bp[0] = pack2(bv0.x); bp[1] = pack2(bv0.y);
            bp[2] = pack2(bv0.z); bp[3] = pack2(bv0.w);
            bp[4] = pack2(bv1.x); bp[5] = pack2(bv1.y);
            bp[6] = pack2(bv1.z); bp[7] = pack2(bv1.w);
#pragma unroll
            for (int ip = 0; ip < 4; ip++)
#pragma unroll
                for (int j = 0; j < 8; j++) ffma2(acc[ip][j], aP[ip], bp[j]);
        }
        __syncthreads();
    }

    float bias0[4], bias1[4];
#pragma unroll
    for (int j = 0; j < 4; j++) {
        bias0[j] = __ldg(&bias[hbase + tx * 4 + j]);
        bias1[j] = __ldg(&bias[hbase + 64 + tx * 4 + j]);
    }
#pragma unroll
    for (int ip = 0; ip < 4; ip++) {
        const int m_l = (ip < 2) ? (ty * 4 + ip * 2) : (64 + ty * 4 + (ip - 2) * 2);
        float2 c0 = up2(acc[ip][0]), c1 = up2(acc[ip][1]);
        float2 c2 = up2(acc[ip][2]), c3 = up2(acc[ip][3]);
        float2 c4 = up2(acc[ip][4]), c5 = up2(acc[ip][5]);
        float2 c6 = up2(acc[ip][6]), c7 = up2(acc[ip][7]);
#pragma unroll
        for (int lane = 0; lane < 2; lane++) {
            const int row = m0 + m_l + lane;        // row = b*512 + t
            const int b = row >> 9, t = row & 511;
            float* dst = g_P + ((size_t)(t * B_ + b)) * 2048 + (size_t)gate * 512 + hbase;
            float4 v0, v1;
            if (lane == 0) {
                v0 = make_float4(c0.x + bias0[0], c1.x + bias0[1], c2.x + bias0[2], c3.x + bias0[3]);
                v1 = make_float4(c4.x + bias1[0], c5.x + bias1[1], c6.x + bias1[2], c7.x + bias1[3]);
            } else {
                v0 = make_float4(c0.y + bias0[0], c1.y + bias0[1], c2.y + bias0[2], c3.y + bias0[3]);
                v1 = make_float4(c4.y + bias1[0], c5.y + bias1[1], c6.y + bias1[2], c7.y + bias1[3]);
            }
            *(float4*)(dst + tx * 4)      = v0;
            *(float4*)(dst + 64 + tx * 4) = v1;
        }
    }
}

// ---------------- phase 2: persistent recurrence (R9 core) ----------------
// 128 CTAs = 4 bg x 32 hg. CTA tile: 16 b x 16 h. 256 threads.
// Thread: h_l = tid&15, ks = tid>>4 (32-k slice). U slice = 64 ull registers.
// Batches accumulated in TWO halves of 8 to stay under the 255-reg cap.

#define SH_STRIDE 36                       // floats per sHd row (32 data + 4 pad)
#define SHD_FLOATS (D_ * SH_STRIDE)        // 18432 floats = 73728 B
#define SRED_ULLS  (16 * 16 * 34)          // [ks][h][16b*2 + pad]
#define SMEM_REC   (SHD_FLOATS * 4 + SRED_ULLS * 8)

__global__ void __launch_bounds__(256, 1) lstm_rec(float* __restrict__ out) {
    extern __shared__ __align__(16) char smem[];
    float* sHd  = (float*)smem;                          // [512][36] dup pairs
    ull*   sRed = (ull*)(smem + SHD_FLOATS * 4);         // [16 ks][16 h][34]

    const int tid = threadIdx.x;
    const int hg = blockIdx.x & 31, bg = blockIdx.x >> 5;
    const int h0 = hg * 16, b0 = bg * 16;
    const int h_l = tid & 15, ks = tid >> 4;             // ks doubles as epilogue b
    const int kbase = ks * 32;
    unsigned* bar = &g_cnt[bg * 32];

    // prologue: U slice into registers (lives across all 512 steps)
    ull uA[32], uB[32];
#pragma unroll
    for (int i = 0; i < 32; i++) {
        ulonglong2 v = g_U4[(size_t)(kbase + i) * H_ + h0 + h_l];
        uA[i] = v.x;                                     // (Uc, Ui)
        uB[i] = v.y;                                     // (Uf, Uo)
    }

    float c_reg = 0.f;
    const float* Pbase = g_P + (size_t)(b0 + ks) * 2048 + h0 + h_l;

    // preload P[0]; later steps prefetched from inside the epilogue
    float p0 = __ldg(Pbase);
    float p1 = __ldg(Pbase + 512);
    float p2 = __ldg(Pbase + 1024);
    float p3 = __ldg(Pbase + 1536);

    for (int t = 0; t < T_; t++) {
        // stage h_{t-1}: global [h][b] -> smem duplicated pairs {h,h}
        // (issue all 8 LDG.128 first for MLP, then store)
        {
            const float* hb = g_h2[t & 1];
            float4 v[8];
#pragma unroll
            for (int j = 0; j < 8; j++) {
                int task = tid + j * 256;
                int k = task >> 2, q = task & 3;
                v[j] = *(const float4*)(hb + (size_t)k * B_ + b0 + q * 4);
            }
#pragma unroll
            for (int j = 0; j < 8; j++) {
                int task = tid + j * 256;
                int k = task >> 2, q = task & 3;
                *(float4*)&sHd[k * SH_STRIDE + q * 8] =
                    make_float4(v[j].x, v[j].x, v[j].y, v[j].y);
                *(float4*)&sHd[k * SH_STRIDE + q * 8 + 4] =
                    make_float4(v[j].z, v[j].z, v[j].w, v[j].w);
            }
        }
        __syncthreads();

        // partial gate sums over this thread's 32-k slice; batches in 2 halves
        ull* rb = sRed + (ks * 16 + h_l) * 34;
#pragma unroll
        for (int half = 0; half < 2; half++) {
            ull acc[8][2];
#pragma unroll
            for (int b = 0; b < 8; b++) { acc[b][0] = 0ull; acc[b][1] = 0ull; }

#pragma unroll
            for (int i = 0; i < 32; i++) {
                const ulonglong2* row =
                    (const ulonglong2*)&sHd[(kbase + i) * SH_STRIDE] + half * 4;
                ull ua = uA[i], ub = uB[i];
#pragma unroll
                for (int bq = 0; bq < 4; bq++) {
                    ulonglong2 hp = row[bq];            // {h dup, h' dup}
                    ffma2(acc[2 * bq][0],     hp.x, ua);
                    ffma2(acc[2 * bq][1],     hp.x, ub);
                    ffma2(acc[2 * bq + 1][0], hp.y, ua);
                    ffma2(acc[2 * bq + 1][1], hp.y, ub);
                }
            }
#pragma unroll
            for (int b = 0; b < 8; b++) {
                rb[(half * 8 + b) * 2]     = acc[b][0];
                rb[(half * 8 + b) * 2 + 1] = acc[b][1];
            }
        }
        __syncthreads();

        // epilogue: thread owns (b = ks, h = h_l)
        {
            float pc = p0, pi = p1, pf = p2, po = p3;

            // prefetch next step's P NOW -> latency hides behind the barrier
            if (t + 1 < T_) {
                const float* Pn = Pbase + (size_t)(t + 1) * B_ * 2048;
                p0 = __ldg(Pn);
                p1 = __ldg(Pn + 512);
                p2 = __ldg(Pn + 1024);
                p3 = __ldg(Pn + 1536);
            }

#pragma unroll
            for (int kk = 0; kk < 16; kk++) {
                const ull* r = sRed + (kk * 16 + h_l) * 34 + 2 * ks;
                float2 v0 = up2(r[0]);
                float2 v1 = up2(r[1]);
                pc += v0.x; pi += v0.y; pf += v1.x; po += v1.y;
            }
            float a  = tanhf(pc);
            float ig = 1.f / (1.f + __expf(-pi));
            float fg = 1.f / (1.f + __expf(-pf));
            float og = 1.f / (1.f + __expf(-po));
            c_reg = ig * a + fg * c_reg;
            float hn = og * tanhf(c_reg);

            g_h2[(t + 1) & 1][(size_t)(h0 + h_l) * B_ + b0 + ks] = hn;
            out[((size_t)(b0 + ks) * T_ + t) * H_ + h0 + h_l] = hn;
        }

        // inter-CTA barrier (release/acquire; bar.sync provides CTA-wide HB)
        if (t < T_ - 1) {
            __syncthreads();
            if (tid == 0) {
                asm volatile("red.release.gpu.global.add.u32 [%0], 1;"
                             :: "l"(bar) : "memory");
                unsigned v, target = 32u * (unsigned)(t + 1);
                do {
                    asm volatile("ld.acquire.gpu.global.u32 %0, [%1];"
                                 : "=r"(v) : "l"(bar) : "memory");
                } while (v < target);
            }
            __syncthreads();
        }
    }
}

// ---------------- launch ----------------
extern "C" void kernel_launch(void* const* d_in, const int* in_sizes, int n_in,
                              void* d_out, int out_size) {
    const float* x  = (const float*)d_in[0];
    const float* Wc = (const float*)d_in[1];
    const float* Wi = (const float*)d_in[2];
    const float* Wf = (const float*)d_in[3];
    const float* Wo = (const float*)d_in[4];
    const float* Uc = (const float*)d_in[5];
    const float* Ui = (const float*)d_in[6];
    const float* Uf = (const float*)d_in[7];
    const float* Uo = (const float*)d_in[8];
    const float* bc = (const float*)d_in[9];
    const float* bi = (const float*)d_in[10];
    const float* bf = (const float*)d_in[11];
    const float* bo = (const float*)d_in[12];
    float* out = (float*)d_out;

    static bool attr_set = false;
    if (!attr_set) {
        cudaFuncSetAttribute(lstm_rec, cudaFuncAttributeMaxDynamicSharedMemorySize, SMEM_REC);
        attr_set = true;
    }

    zero_init<<<128, 256>>>();
    build_u4<<<(D_ * H_) / 256, 256>>>(Uc, Ui, Uf, Uo);

    dim3 ggrid(2048 / BN, (B_ * T_) / BM);   // (16, 256)
    gemm_pre<<<ggrid, 256>>>(x, Wc, Wi, Wf, Wo, bc, bi, bf, bo);

    lstm_rec<<<128, 256, SMEM_REC>>>(out);
}

// round 16
// speedup vs baseline: 1.3452x; 1.0867x over previous
#include <cuda_runtime.h>
#include <cuda_bf16.h>
#include <cstdint>
#include <cstddef>

// LSTM: B=64, T=512, D=512, H=512, fp32.
// Phase 0: interleave U gates; build bf16 hi/lo split A' (x) and B' (W).
// Phase 1: P = A' @ B'^T + bias via mma.sync bf16 (K=1536 concat, fp32 acc).
// Phase 2: persistent recurrence (R14 core, unchanged).

typedef unsigned long long ull;

#define B_ 64
#define T_ 512
#define D_ 512
#define H_ 512
#define KTOT 1536
#define NCH  48          // K chunks of 32

// ---------------- device scratch (static: no allocation APIs) ----------------
__device__ float          g_P[(size_t)T_ * B_ * 2048];
__device__ ulonglong2     g_U4[(size_t)D_ * H_];
__device__ float          g_h2[2][(size_t)H_ * B_];
__device__ unsigned       g_cnt[4 * 32];
__device__ __nv_bfloat16  g_Abf[(size_t)B_ * T_ * KTOT];   // [m][1536]=[xh|xl|xh]
__device__ __nv_bfloat16  g_Bbf[(size_t)2048 * KTOT];      // [n][1536]=[wh|wh|wl]

// ---------------- helpers ----------------
__device__ __forceinline__ void ffma2(ull& d, ull a, ull b) {
    asm("fma.rn.f32x2 %0, %1, %2, %0;" : "+l"(d) : "l"(a), "l"(b));
}
__device__ __forceinline__ float2 up2(ull v) {
    float2 r; asm("mov.b64 {%0, %1}, %2;" : "=f"(r.x), "=f"(r.y) : "l"(v)); return r;
}
__device__ __forceinline__ uint32_t smem_u32(const void* p) {
    uint32_t a;
    asm("{ .reg .u64 t; cvta.to.shared.u64 t, %1; cvt.u32.u64 %0, t; }"
        : "=r"(a) : "l"(p));
    return a;
}

#define LDMX4(r0, r1, r2, r3, addr)                                         \
    asm volatile("ldmatrix.sync.aligned.m8n8.x4.shared.b16 {%0,%1,%2,%3}, [%4];" \
                 : "=r"(r0), "=r"(r1), "=r"(r2), "=r"(r3) : "r"(addr))

#define MMA16816(c, a0, a1, a2, a3, b0, b1)                                 \
    asm volatile("mma.sync.aligned.m16n8k16.row.col.f32.bf16.bf16.f32 "      \
                 "{%0,%1,%2,%3}, {%4,%5,%6,%7}, {%8,%9}, {%0,%1,%2,%3};"     \
                 : "+f"((c)[0]), "+f"((c)[1]), "+f"((c)[2]), "+f"((c)[3])    \
                 : "r"(a0), "r"(a1), "r"(a2), "r"(a3), "r"(b0), "r"(b1))

// ---------------- phase 0 ----------------
__global__ void build_u4(const float* __restrict__ Uc, const float* __restrict__ Ui,
                         const float* __restrict__ Uf, const float* __restrict__ Uo) {
    int i = blockIdx.x * 256 + threadIdx.x;
    float4 v = make_float4(Uc[i], Ui[i], Uf[i], Uo[i]);
    ((float4*)g_U4)[i] = v;
}

__global__ void zero_init() {
    int i = blockIdx.x * 256 + threadIdx.x;
    g_h2[0][i] = 0.f;
    if (i < 4 * 32) g_cnt[i] = 0u;
}

__global__ void build_abf(const float* __restrict__ x) {
    int i = blockIdx.x * 256 + threadIdx.x;        // over 32768*512
    int m = i >> 9, k = i & 511;
    float v = x[i];
    __nv_bfloat16 hi = __float2bfloat16(v);
    __nv_bfloat16 lo = __float2bfloat16(v - __bfloat162float(hi));
    __nv_bfloat16* row = g_Abf + (size_t)m * KTOT;
    row[k] = hi;
    row[512 + k] = lo;
    row[1024 + k] = hi;
}

__global__ void build_bbf(const float* __restrict__ Wc, const float* __restrict__ Wi,
                          const float* __restrict__ Wf, const float* __restrict__ Wo) {
    int i = blockIdx.x * 256 + threadIdx.x;        // over 4*512*512
    int gate = i >> 18;
    int rem  = i & 262143;
    int k = rem >> 9, h = rem & 511;
    const float* W = (gate == 0) ? Wc : (gate == 1) ? Wi : (gate == 2) ? Wf : Wo;
    float v = W[k * 512 + h];
    __nv_bfloat16 hi = __float2bfloat16(v);
    __nv_bfloat16 lo = __float2bfloat16(v - __bfloat162float(hi));
    __nv_bfloat16* row = g_Bbf + (size_t)(gate * 512 + h) * KTOT;
    row[k] = hi;
    row[512 + k] = hi;
    row[1024 + k] = lo;
}

// ---------------- phase 1: mma.sync bf16 GEMM ----------------
// C[m][n] = sum_k A'[m][k] B'[n][k]. BM=BN=128, BK=32, 256 thr (8 warps 2mx4n).
// Warp tile 64x32: 4 m-frags (16) x 4 n-frags (8), k-steps of 16.
#define LDP 40        // padded smem row length (bf16)

__global__ void __launch_bounds__(256, 1) gemm_tc(
    const float* __restrict__ bc, const float* __restrict__ bi,
    const float* __restrict__ bf_, const float* __restrict__ bo) {
    __shared__ __align__(16) __nv_bfloat16 As[2][128][LDP];
    __shared__ __align__(16) __nv_bfloat16 Bs[2][128][LDP];
    __shared__ float sbias[128];

    const int tid  = threadIdx.x;
    const int lane = tid & 31;
    const int wid  = tid >> 5;
    const int wm   = wid >> 2;          // 0..1  (64 rows each)
    const int wn   = wid & 3;           // 0..3  (32 cols each)
    const int n0 = blockIdx.x * 128;
    const int m0 = blockIdx.y * 128;

    {
        const int gate = n0 >> 9, hc = n0 & 511;
        const float* bias = (gate == 0) ? bc : (gate == 1) ? bi
                           : (gate == 2) ? bf_ : bo;
        if (tid < 128) sbias[tid] = __ldg(&bias[hc + tid]);
    }

    const __nv_bfloat16* Ar = g_Abf + (size_t)m0 * KTOT;
    const __nv_bfloat16* Br = g_Bbf + (size_t)n0 * KTOT;

    // staging task: idx = tid + it*256; r = idx>>2 (row), c = idx&3 (16B unit)
    const int r0t = tid >> 2, c0t = tid & 3;

    // stage chunk 0
#pragma unroll
    for (int it = 0; it < 2; it++) {
        int r = r0t + it * 64, c = c0t;
        *(uint4*)&As[0][r][c * 8] = *(const uint4*)(Ar + (size_t)r * KTOT + c * 8);
        *(uint4*)&Bs[0][r][c * 8] = *(const uint4*)(Br + (size_t)r * KTOT + c * 8);
    }
    __syncthreads();

    float acc[4][4][4];
#pragma unroll
    for (int f = 0; f < 4; f++)
#pragma unroll
        for (int n = 0; n < 4; n++)
#pragma unroll
            for (int e = 0; e < 4; e++) acc[f][n][e] = 0.f;

    // ldmatrix lane-address components
    const int aRow = lane & 15;                       // m row within 16
    const int aCol = (lane >> 4) * 8;                 // k half
    const int bRow = (lane & 7) + ((lane >> 4) << 3); // n row within 16
    const int bCol = ((lane >> 3) & 1) * 8;           // k half

    const uint32_t sA = smem_u32(&As[0][0][0]);
    const uint32_t sB = smem_u32(&Bs[0][0][0]);
    const uint32_t bufStride = 128 * LDP * 2;         // bytes per buffer

    for (int ch = 0; ch < NCH; ch++) {
        const int cur = ch & 1;

        uint4 va[2], vb[2];
        if (ch + 1 < NCH) {
#pragma unroll
            for (int it = 0; it < 2; it++) {
                int r = r0t + it * 64, c = c0t;
                va[it] = *(const uint4*)(Ar + (size_t)r * KTOT + (ch + 1) * 32 + c * 8);
                vb[it] = *(const uint4*)(Br + (size_t)r * KTOT + (ch + 1) * 32 + c * 8);
            }
        }

        // compute on buffer cur
        const uint32_t aB = sA + cur * bufStride;
        const uint32_t bB = sB + cur * bufStride;
#pragma unroll
        for (int kk2 = 0; kk2 < 2; kk2++) {
            const int kk = kk2 * 16;
            uint32_t af[4][4];
#pragma unroll
            for (int f = 0; f < 4; f++) {
                uint32_t addr = aB +
                    ((wm * 64 + f * 16 + aRow) * LDP + kk + aCol) * 2;
                LDMX4(af[f][0], af[f][1], af[f][2], af[f][3], addr);
            }
            uint32_t bfr[2][4];
#pragma unroll
            for (int g = 0; g < 2; g++) {
                uint32_t addr = bB +
                    ((wn * 32 + g * 16 + bRow) * LDP + kk + bCol) * 2;
                LDMX4(bfr[g][0], bfr[g][1], bfr[g][2], bfr[g][3], addr);
            }
#pragma unroll
            for (int f = 0; f < 4; f++) {
#pragma unroll
                for (int g = 0; g < 2; g++) {
#pragma unroll
                    for (int sub = 0; sub < 2; sub++) {
                        MMA16816(acc[f][g * 2 + sub],
                                 af[f][0], af[f][1], af[f][2], af[f][3],
                                 bfr[g][2 * sub], bfr[g][2 * sub + 1]);
                    }
                }
            }
        }

        if (ch + 1 < NCH) {
            const int nb = 1 - cur;
#pragma unroll
            for (int it = 0; it < 2; it++) {
                int r = r0t + it * 64, c = c0t;
                *(uint4*)&As[nb][r][c * 8] = va[it];
                *(uint4*)&Bs[nb][r][c * 8] = vb[it];
            }
        }
        __syncthreads();
    }

    // epilogue: add bias, scatter to g_P[t][b][gate*512+h]
#pragma unroll
    for (int f = 0; f < 4; f++) {
#pragma unroll
        for (int nf = 0; nf < 4; nf++) {
            const int colT = wn * 32 + nf * 8 + 2 * (lane & 3);
            const float bx = sbias[colT], by = sbias[colT + 1];
#pragma unroll
            for (int half = 0; half < 2; half++) {
                const int row = m0 + wm * 64 + f * 16 + (lane >> 2) + half * 8;
                const int b = row >> 9, t = row & 511;
                float* dst = g_P + ((size_t)(t * B_ + b)) * 2048 + n0 + colT;
                float2 v;
                v.x = acc[f][nf][half * 2 + 0] + bx;
                v.y = acc[f][nf][half * 2 + 1] + by;
                *(float2*)dst = v;
            }
        }
    }
}

// ---------------- phase 2: persistent recurrence (R14 core) ----------------
#define SH_STRIDE 36
#define SHD_FLOATS (D_ * SH_STRIDE)
#define SRED_ULLS  (16 * 16 * 34)
#define SMEM_REC   (SHD_FLOATS * 4 + SRED_ULLS * 8)

__global__ void __launch_bounds__(256, 1) lstm_rec(float* __restrict__ out) {
    extern __shared__ __align__(16) char smem[];
    float* sHd  = (float*)smem;
    ull*   sRed = (ull*)(smem + SHD_FLOATS * 4);

    const int tid = threadIdx.x;
    const int hg = blockIdx.x & 31, bg = blockIdx.x >> 5;
    const int h0 = hg * 16, b0 = bg * 16;
    const int h_l = tid & 15, ks = tid >> 4;
    const int kbase = ks * 32;
    unsigned* bar = &g_cnt[bg * 32];

    ull uA[32], uB[32];
#pragma unroll
    for (int i = 0; i < 32; i++) {
        ulonglong2 v = g_U4[(size_t)(kbase + i) * H_ + h0 + h_l];
        uA[i] = v.x;
        uB[i] = v.y;
    }

    float c_reg = 0.f;
    const float* Pbase = g_P + (size_t)(b0 + ks) * 2048 + h0 + h_l;

    float p0 = __ldg(Pbase);
    float p1 = __ldg(Pbase + 512);
    float p2 = __ldg(Pbase + 1024);
    float p3 = __ldg(Pbase + 1536);

    for (int t = 0; t < T_; t++) {
        {
            const float* hb = g_h2[t & 1];
            float4 v[8];
#pragma unroll
            for (int j = 0; j < 8; j++) {
                int task = tid + j * 256;
                int k = task >> 2, q = task & 3;
                v[j] = *(const float4*)(hb + (size_t)k * B_ + b0 + q * 4);
            }
#pragma unroll
            for (int j = 0; j < 8; j++) {
                int task = tid + j * 256;
                int k = task >> 2, q = task & 3;
                *(float4*)&sHd[k * SH_STRIDE + q * 8] =
                    make_float4(v[j].x, v[j].x, v[j].y, v[j].y);
                *(float4*)&sHd[k * SH_STRIDE + q * 8 + 4] =
                    make_float4(v[j].z, v[j].z, v[j].w, v[j].w);
            }
        }
        __syncthreads();

        ull* rb = sRed + (ks * 16 + h_l) * 34;
#pragma unroll
        for (int half = 0; half < 2; half++) {
            ull acc[8][2];
#pragma unroll
            for (int b = 0; b < 8; b++) { acc[b][0] = 0ull; acc[b][1] = 0ull; }

#pragma unroll
            for (int i = 0; i < 32; i++) {
                const ulonglong2* row =
                    (const ulonglong2*)&sHd[(kbase + i) * SH_STRIDE] + half * 4;
                ull ua = uA[i], ub = uB[i];
#pragma unroll
                for (int bq = 0; bq < 4; bq++) {
                    ulonglong2 hp = row[bq];
                    ffma2(acc[2 * bq][0],     hp.x, ua);
                    ffma2(acc[2 * bq][1],     hp.x, ub);
                    ffma2(acc[2 * bq + 1][0], hp.y, ua);
                    ffma2(acc[2 * bq + 1][1], hp.y, ub);
                }
            }
#pragma unroll
            for (int b = 0; b < 8; b++) {
                rb[(half * 8 + b) * 2]     = acc[b][0];
                rb[(half * 8 + b) * 2 + 1] = acc[b][1];
            }
        }
        __syncthreads();

        {
            float pc = p0, pi = p1, pf = p2, po = p3;
            if (t + 1 < T_) {
                const float* Pn = Pbase + (size_t)(t + 1) * B_ * 2048;
                p0 = __ldg(Pn);
                p1 = __ldg(Pn + 512);
                p2 = __ldg(Pn + 1024);
                p3 = __ldg(Pn + 1536);
            }
#pragma unroll
            for (int kk = 0; kk < 16; kk++) {
                const ull* r = sRed + (kk * 16 + h_l) * 34 + 2 * ks;
                float2 v0 = up2(r[0]);
                float2 v1 = up2(r[1]);
                pc += v0.x; pi += v0.y; pf += v1.x; po += v1.y;
            }
            float a  = tanhf(pc);
            float ig = 1.f / (1.f + __expf(-pi));
            float fg = 1.f / (1.f + __expf(-pf));
            float og = 1.f / (1.f + __expf(-po));
            c_reg = ig * a + fg * c_reg;
            float hn = og * tanhf(c_reg);

            g_h2[(t + 1) & 1][(size_t)(h0 + h_l) * B_ + b0 + ks] = hn;
            out[((size_t)(b0 + ks) * T_ + t) * H_ + h0 + h_l] = hn;
        }

        if (t < T_ - 1) {
            __syncthreads();
            if (tid == 0) {
                asm volatile("red.release.gpu.global.add.u32 [%0], 1;"
                             :: "l"(bar) : "memory");
                unsigned v, target = 32u * (unsigned)(t + 1);
                do {
                    asm volatile("ld.acquire.gpu.global.u32 %0, [%1];"
                                 : "=r"(v) : "l"(bar) : "memory");
                } while (v < target);
            }
            __syncthreads();
        }
    }
}

// ---------------- launch ----------------
extern "C" void kernel_launch(void* const* d_in, const int* in_sizes, int n_in,
                              void* d_out, int out_size) {
    const float* x  = (const float*)d_in[0];
    const float* Wc = (const float*)d_in[1];
    const float* Wi = (const float*)d_in[2];
    const float* Wf = (const float*)d_in[3];
    const float* Wo = (const float*)d_in[4];
    const float* Uc = (const float*)d_in[5];
    const float* Ui = (const float*)d_in[6];
    const float* Uf = (const float*)d_in[7];
    const float* Uo = (const float*)d_in[8];
    const float* bc = (const float*)d_in[9];
    const float* bi = (const float*)d_in[10];
    const float* bf = (const float*)d_in[11];
    const float* bo = (const float*)d_in[12];
    float* out = (float*)d_out;

    static bool attr_set = false;
    if (!attr_set) {
        cudaFuncSetAttribute(lstm_rec, cudaFuncAttributeMaxDynamicSharedMemorySize, SMEM_REC);
        attr_set = true;
    }

    zero_init<<<128, 256>>>();
    build_u4<<<(D_ * H_) / 256, 256>>>(Uc, Ui, Uf, Uo);
    build_abf<<<(B_ * T_ * D_) / 256, 256>>>(x);
    build_bbf<<<(4 * D_ * H_) / 256, 256>>>(Wc, Wi, Wf, Wo);

    dim3 ggrid(2048 / 128, (B_ * T_) / 128);   // (16, 256)
    gemm_tc<<<ggrid, 256>>>(bc, bi, bf, bo);

    lstm_rec<<<128, 256, SMEM_REC>>>(out);
}

// round 17
// speedup vs baseline: 1.6736x; 1.2441x over previous
#include <cuda_runtime.h>
#include <cuda_bf16.h>
#include <cstdint>
#include <cstddef>

// LSTM: B=64, T=512, D=512, H=512, fp32.
// Phase 0: bf16 hi/lo splits: A'(x) [m][1536], B'(W) [n][1536], U -> Uh/Ul [n=2048][k=512].
// Phase 1: P = A' @ B'^T + bias via mma.sync bf16 (fp32 acc)      [R16, validated]
// Phase 2: persistent recurrence, per-step h@U via mma.sync bf16 hi/lo (3 terms),
//          full-K per warp (no cross-warp reduction), ~60 regs.

typedef unsigned long long ull;

#define B_ 64
#define T_ 512
#define D_ 512
#define H_ 512
#define KTOT 1536
#define NCH  48

// ---------------- device scratch ----------------
__device__ float          g_P[(size_t)T_ * B_ * 2048];
__device__ float          g_h2[2][(size_t)B_ * H_];        // [b][h]
__device__ unsigned       g_cnt[4 * 32];
__device__ __nv_bfloat16  g_Abf[(size_t)B_ * T_ * KTOT];   // [m][1536]=[xh|xl|xh]
__device__ __nv_bfloat16  g_Bbf[(size_t)2048 * KTOT];      // [n][1536]=[wh|wh|wl]
__device__ __nv_bfloat16  g_Uh[(size_t)2048 * 512];        // [gate*512+h][k]
__device__ __nv_bfloat16  g_Ul[(size_t)2048 * 512];

// ---------------- helpers ----------------
__device__ __forceinline__ uint32_t smem_u32(const void* p) {
    uint32_t a;
    asm("{ .reg .u64 t; cvta.to.shared.u64 t, %1; cvt.u32.u64 %0, t; }"
        : "=r"(a) : "l"(p));
    return a;
}

#define LDMX4(r0, r1, r2, r3, addr)                                         \
    asm volatile("ldmatrix.sync.aligned.m8n8.x4.shared.b16 {%0,%1,%2,%3}, [%4];" \
                 : "=r"(r0), "=r"(r1), "=r"(r2), "=r"(r3) : "r"(addr))

#define LDMX2(r0, r1, addr)                                                 \
    asm volatile("ldmatrix.sync.aligned.m8n8.x2.shared.b16 {%0,%1}, [%2];"   \
                 : "=r"(r0), "=r"(r1) : "r"(addr))

#define MMA16816(c, a0, a1, a2, a3, b0, b1)                                 \
    asm volatile("mma.sync.aligned.m16n8k16.row.col.f32.bf16.bf16.f32 "      \
                 "{%0,%1,%2,%3}, {%4,%5,%6,%7}, {%8,%9}, {%0,%1,%2,%3};"     \
                 : "+f"((c)[0]), "+f"((c)[1]), "+f"((c)[2]), "+f"((c)[3])    \
                 : "r"(a0), "r"(a1), "r"(a2), "r"(a3), "r"(b0), "r"(b1))

// ---------------- phase 0 ----------------
__global__ void zero_init() {
    int i = blockIdx.x * 256 + threadIdx.x;
    g_h2[0][i] = 0.f;
    if (i < 4 * 32) g_cnt[i] = 0u;
}

__global__ void build_abf(const float* __restrict__ x) {
    int i = blockIdx.x * 256 + threadIdx.x;        // over 32768*512
    int m = i >> 9, k = i & 511;
    float v = x[i];
    __nv_bfloat16 hi = __float2bfloat16(v);
    __nv_bfloat16 lo = __float2bfloat16(v - __bfloat162float(hi));
    __nv_bfloat16* row = g_Abf + (size_t)m * KTOT;
    row[k] = hi;
    row[512 + k] = lo;
    row[1024 + k] = hi;
}

__global__ void build_bbf(const float* __restrict__ Wc, const float* __restrict__ Wi,
                          const float* __restrict__ Wf, const float* __restrict__ Wo) {
    int i = blockIdx.x * 256 + threadIdx.x;        // over 4*512*512
    int gate = i >> 18;
    int rem  = i & 262143;
    int k = rem >> 9, h = rem & 511;
    const float* W = (gate == 0) ? Wc : (gate == 1) ? Wi : (gate == 2) ? Wf : Wo;
    float v = W[k * 512 + h];
    __nv_bfloat16 hi = __float2bfloat16(v);
    __nv_bfloat16 lo = __float2bfloat16(v - __bfloat162float(hi));
    __nv_bfloat16* row = g_Bbf + (size_t)(gate * 512 + h) * KTOT;
    row[k] = hi;
    row[512 + k] = hi;
    row[1024 + k] = lo;
}

// tiled transpose: U_g[k][h] -> g_Uh/g_Ul[(gate*512+h)][k] (bf16 hi/lo)
__global__ void build_ubf(const float* __restrict__ Uc, const float* __restrict__ Ui,
                          const float* __restrict__ Uf, const float* __restrict__ Uo) {
    __shared__ float tile[32][33];
    const int gate = blockIdx.z;
    const float* U = (gate == 0) ? Uc : (gate == 1) ? Ui : (gate == 2) ? Uf : Uo;
    const int kt = blockIdx.x * 32, ht = blockIdx.y * 32;
    const int tx = threadIdx.x & 31, ty = threadIdx.x >> 5;   // 32 x 8

#pragma unroll
    for (int j = 0; j < 4; j++)
        tile[ty + j * 8][tx] = U[(size_t)(kt + ty + j * 8) * 512 + ht + tx];
    __syncthreads();
#pragma unroll
    for (int j = 0; j < 4; j++) {
        int hl = ty + j * 8;
        float v = tile[tx][hl];
        __nv_bfloat16 hi = __float2bfloat16(v);
        __nv_bfloat16 lo = __float2bfloat16(v - __bfloat162float(hi));
        size_t off = (size_t)(gate * 512 + ht + hl) * 512 + kt + tx;
        g_Uh[off] = hi;
        g_Ul[off] = lo;
    }
}

// ---------------- phase 1: mma.sync bf16 GEMM (R16, validated) ----------------
#define LDP 40

__global__ void __launch_bounds__(256, 1) gemm_tc(
    const float* __restrict__ bc, const float* __restrict__ bi,
    const float* __restrict__ bf_, const float* __restrict__ bo) {
    __shared__ __align__(16) __nv_bfloat16 As[2][128][LDP];
    __shared__ __align__(16) __nv_bfloat16 Bs[2][128][LDP];
    __shared__ float sbias[128];

    const int tid  = threadIdx.x;
    const int lane = tid & 31;
    const int wid  = tid >> 5;
    const int wm   = wid >> 2;
    const int wn   = wid & 3;
    const int n0 = blockIdx.x * 128;
    const int m0 = blockIdx.y * 128;

    {
        const int gate = n0 >> 9, hc = n0 & 511;
        const float* bias = (gate == 0) ? bc : (gate == 1) ? bi
                           : (gate == 2) ? bf_ : bo;
        if (tid < 128) sbias[tid] = __ldg(&bias[hc + tid]);
    }

    const __nv_bfloat16* Ar = g_Abf + (size_t)m0 * KTOT;
    const __nv_bfloat16* Br = g_Bbf + (size_t)n0 * KTOT;

    const int r0t = tid >> 2, c0t = tid & 3;

#pragma unroll
    for (int it = 0; it < 2; it++) {
        int r = r0t + it * 64, c = c0t;
        *(uint4*)&As[0][r][c * 8] = *(const uint4*)(Ar + (size_t)r * KTOT + c * 8);
        *(uint4*)&Bs[0][r][c * 8] = *(const uint4*)(Br + (size_t)r * KTOT + c * 8);
    }
    __syncthreads();

    float acc[4][4][4];
#pragma unroll
    for (int f = 0; f < 4; f++)
#pragma unroll
        for (int n = 0; n < 4; n++)
#pragma unroll
            for (int e = 0; e < 4; e++) acc[f][n][e] = 0.f;

    const int aRow = lane & 15;
    const int aCol = (lane >> 4) * 8;
    const int bRow = (lane & 7) + ((lane >> 4) << 3);
    const int bCol = ((lane >> 3) & 1) * 8;

    const uint32_t sA = smem_u32(&As[0][0][0]);
    const uint32_t sB = smem_u32(&Bs[0][0][0]);
    const uint32_t bufStride = 128 * LDP * 2;

    for (int ch = 0; ch < NCH; ch++) {
        const int cur = ch & 1;

        uint4 va[2], vb[2];
        if (ch + 1 < NCH) {
#pragma unroll
            for (int it = 0; it < 2; it++) {
                int r = r0t + it * 64, c = c0t;
                va[it] = *(const uint4*)(Ar + (size_t)r * KTOT + (ch + 1) * 32 + c * 8);
                vb[it] = *(const uint4*)(Br + (size_t)r * KTOT + (ch + 1) * 32 + c * 8);
            }
        }

        const uint32_t aB = sA + cur * bufStride;
        const uint32_t bB = sB + cur * bufStride;
#pragma unroll
        for (int kk2 = 0; kk2 < 2; kk2++) {
            const int kk = kk2 * 16;
            uint32_t af[4][4];
#pragma unroll
            for (int f = 0; f < 4; f++) {
                uint32_t addr = aB + ((wm * 64 + f * 16 + aRow) * LDP + kk + aCol) * 2;
                LDMX4(af[f][0], af[f][1], af[f][2], af[f][3], addr);
            }
            uint32_t bfr[2][4];
#pragma unroll
            for (int g = 0; g < 2; g++) {
                uint32_t addr = bB + ((wn * 32 + g * 16 + bRow) * LDP + kk + bCol) * 2;
                LDMX4(bfr[g][0], bfr[g][1], bfr[g][2], bfr[g][3], addr);
            }
#pragma unroll
            for (int f = 0; f < 4; f++)
#pragma unroll
                for (int g = 0; g < 2; g++)
#pragma unroll
                    for (int sub = 0; sub < 2; sub++)
                        MMA16816(acc[f][g * 2 + sub],
                                 af[f][0], af[f][1], af[f][2], af[f][3],
                                 bfr[g][2 * sub], bfr[g][2 * sub + 1]);
        }

        if (ch + 1 < NCH) {
            const int nb = 1 - cur;
#pragma unroll
            for (int it = 0; it < 2; it++) {
                int r = r0t + it * 64, c = c0t;
                *(uint4*)&As[nb][r][c * 8] = va[it];
                *(uint4*)&Bs[nb][r][c * 8] = vb[it];
            }
        }
        __syncthreads();
    }

#pragma unroll
    for (int f = 0; f < 4; f++) {
#pragma unroll
        for (int nf = 0; nf < 4; nf++) {
            const int colT = wn * 32 + nf * 8 + 2 * (lane & 3);
            const float bx = sbias[colT], by = sbias[colT + 1];
#pragma unroll
            for (int half = 0; half < 2; half++) {
                const int row = m0 + wm * 64 + f * 16 + (lane >> 2) + half * 8;
                const int b = row >> 9, t = row & 511;
                float* dst = g_P + ((size_t)(t * B_ + b)) * 2048 + n0 + colT;
                float2 v;
                v.x = acc[f][nf][half * 2 + 0] + bx;
                v.y = acc[f][nf][half * 2 + 1] + by;
                *(float2*)dst = v;
            }
        }
    }
}

// ---------------- phase 2: persistent tensor-core recurrence ----------------
// 128 CTAs = 4 bg x 32 hg, 256 threads (8 warps). CTA: M=16 b, N=64 (4g x 16h), K=512.
// Warp w owns n-slice [8w, 8w+8): 1 m-frag x 1 n-frag x 32 k-steps x 3 hi/lo terms.
// smem: Uh/Ul [64][520] bf16 (staged once), hh/hl [16][520] bf16 (per step), sOut.
#define LDU 520
#define SUH_OFF  0
#define SUL_OFF  66560
#define SHH_OFF  133120
#define SHL_OFF  149760
#define SOUT_OFF 166400
#define SMEM_RTC 170752

__global__ void __launch_bounds__(256, 1) lstm_rec_tc(float* __restrict__ out) {
    extern __shared__ __align__(16) char sm[];
    const uint32_t smb = smem_u32(sm);
    float* sOut = (float*)(sm + SOUT_OFF);               // [64][17]

    const int tid  = threadIdx.x;
    const int lane = tid & 31;
    const int wid  = tid >> 5;
    const int hg = blockIdx.x & 31, bg = blockIdx.x >> 5;
    const int h0 = hg * 16, b0 = bg * 16;
    const int h_l = tid & 15, eb = tid >> 4;
    unsigned* bar = &g_cnt[bg * 32];

    // stage U slice (64 rows: n = gate*16 + j <- global gate*512 + h0 + j)
#pragma unroll
    for (int j = 0; j < 16; j++) {
        int idx = tid + j * 256;                 // 0..4095
        int r = idx >> 6, c = idx & 63;
        int gate = r >> 4, hh_ = r & 15;
        size_t src = (size_t)(gate * 512 + h0 + hh_) * 512 + c * 8;
        *(uint4*)(sm + SUH_OFF + r * (LDU * 2) + c * 16) = *(const uint4*)(g_Uh + src);
        *(uint4*)(sm + SUL_OFF + r * (LDU * 2) + c * 16) = *(const uint4*)(g_Ul + src);
    }

    float c_reg = 0.f;
    const float* Pbase = g_P + (size_t)(b0 + eb) * 2048 + h0 + h_l;
    float p0 = __ldg(Pbase);
    float p1 = __ldg(Pbase + 512);
    float p2 = __ldg(Pbase + 1024);
    float p3 = __ldg(Pbase + 1536);

    // ldmatrix address components (validated R16 patterns)
    const uint32_t aOffH = smb + SHH_OFF + ((lane & 15) * LDU + (lane >> 4) * 8) * 2;
    const uint32_t aOffL = smb + SHL_OFF + ((lane & 15) * LDU + (lane >> 4) * 8) * 2;
    const uint32_t bRowOff = ((wid * 8 + (lane & 7)) * LDU + ((lane >> 3) & 1) * 8) * 2;
    const uint32_t bOffH = smb + SUH_OFF + bRowOff;
    const uint32_t bOffL = smb + SUL_OFF + bRowOff;

    __syncthreads();

    for (int t = 0; t < T_; t++) {
        // stage h_{t-1}: fp32 [b][h] -> bf16 hi/lo smem
        {
            const float* hb = g_h2[t & 1] + (size_t)b0 * 512;
#pragma unroll
            for (int j = 0; j < 8; j++) {
                int task = tid + j * 256;                // 0..2047
                int b_l = task >> 7, c = task & 127;
                float4 v = *(const float4*)(hb + (size_t)b_l * 512 + c * 4);
                __nv_bfloat16 h0b = __float2bfloat16(v.x);
                __nv_bfloat16 h1b = __float2bfloat16(v.y);
                __nv_bfloat16 h2b = __float2bfloat16(v.z);
                __nv_bfloat16 h3b = __float2bfloat16(v.w);
                __nv_bfloat16 l0b = __float2bfloat16(v.x - __bfloat162float(h0b));
                __nv_bfloat16 l1b = __float2bfloat16(v.y - __bfloat162float(h1b));
                __nv_bfloat16 l2b = __float2bfloat16(v.z - __bfloat162float(h2b));
                __nv_bfloat16 l3b = __float2bfloat16(v.w - __bfloat162float(h3b));
                uint2 hu, lu;
                hu.x = (uint32_t)__bfloat16_as_ushort(h0b) |
                       ((uint32_t)__bfloat16_as_ushort(h1b) << 16);
                hu.y = (uint32_t)__bfloat16_as_ushort(h2b) |
                       ((uint32_t)__bfloat16_as_ushort(h3b) << 16);
                lu.x = (uint32_t)__bfloat16_as_ushort(l0b) |
                       ((uint32_t)__bfloat16_as_ushort(l1b) << 16);
                lu.y = (uint32_t)__bfloat16_as_ushort(l2b) |
                       ((uint32_t)__bfloat16_as_ushort(l3b) << 16);
                *(uint2*)(sm + SHH_OFF + b_l * (LDU * 2) + c * 8) = hu;
                *(uint2*)(sm + SHL_OFF + b_l * (LDU * 2) + c * 8) = lu;
            }
        }
        __syncthreads();

        // mma: 32 k-steps x (A hh/hl x4, B Uh/Ul x2, 3 mma)
        float acc[4] = {0.f, 0.f, 0.f, 0.f};
#pragma unroll 8
        for (int ks = 0; ks < 32; ks++) {
            const uint32_t ko = ks * 32;                 // 16 bf16 = 32 B
            uint32_t ah0, ah1, ah2, ah3, al0, al1, al2, al3;
            uint32_t bh0, bh1, bl0, bl1;
            LDMX4(ah0, ah1, ah2, ah3, aOffH + ko);
            LDMX4(al0, al1, al2, al3, aOffL + ko);
            LDMX2(bh0, bh1, bOffH + ko);
            LDMX2(bl0, bl1, bOffL + ko);
            MMA16816(acc, ah0, ah1, ah2, ah3, bh0, bh1);
            MMA16816(acc, al0, al1, al2, al3, bh0, bh1);
            MMA16816(acc, ah0, ah1, ah2, ah3, bl0, bl1);
        }

        // exchange C through sOut[n][b]
        {
            const int m = lane >> 2, cc = (lane & 3) * 2, n0w = wid * 8;
            sOut[(n0w + cc) * 17 + m]          = acc[0];
            sOut[(n0w + cc + 1) * 17 + m]      = acc[1];
            sOut[(n0w + cc) * 17 + m + 8]      = acc[2];
            sOut[(n0w + cc + 1) * 17 + m + 8]  = acc[3];
        }
        __syncthreads();

        // epilogue: thread owns (b = eb, h = h_l)
        {
            float pc = p0 + sOut[h_l * 17 + eb];
            float pi = p1 + sOut[(16 + h_l) * 17 + eb];
            float pf = p2 + sOut[(32 + h_l) * 17 + eb];
            float po = p3 + sOut[(48 + h_l) * 17 + eb];

            if (t + 1 < T_) {
                const float* Pn = Pbase + (size_t)(t + 1) * B_ * 2048;
                p0 = __ldg(Pn);
                p1 = __ldg(Pn + 512);
                p2 = __ldg(Pn + 1024);
                p3 = __ldg(Pn + 1536);
            }

            float a  = tanhf(pc);
            float ig = 1.f / (1.f + __expf(-pi));
            float fg = 1.f / (1.f + __expf(-pf));
            float og = 1.f / (1.f + __expf(-po));
            c_reg = ig * a + fg * c_reg;
            float hn = og * tanhf(c_reg);

            g_h2[(t + 1) & 1][(size_t)(b0 + eb) * 512 + h0 + h_l] = hn;
            out[((size_t)(b0 + eb) * T_ + t) * H_ + h0 + h_l] = hn;
        }

        // inter-CTA barrier, batch-group scope (validated protocol)
        if (t < T_ - 1) {
            __syncthreads();
            if (tid == 0) {
                asm volatile("red.release.gpu.global.add.u32 [%0], 1;"
                             :: "l"(bar) : "memory");
                unsigned v, target = 32u * (unsigned)(t + 1);
                do {
                    asm volatile("ld.acquire.gpu.global.u32 %0, [%1];"
                                 : "=r"(v) : "l"(bar) : "memory");
                } while (v < target);
            }
            __syncthreads();
        }
    }
}

// ---------------- launch ----------------
extern "C" void kernel_launch(void* const* d_in, const int* in_sizes, int n_in,
                              void* d_out, int out_size) {
    const float* x  = (const float*)d_in[0];
    const float* Wc = (const float*)d_in[1];
    const float* Wi = (const float*)d_in[2];
    const float* Wf = (const float*)d_in[3];
    const float* Wo = (const float*)d_in[4];
    const float* Uc = (const float*)d_in[5];
    const float* Ui = (const float*)d_in[6];
    const float* Uf = (const float*)d_in[7];
    const float* Uo = (const float*)d_in[8];
    const float* bc = (const float*)d_in[9];
    const float* bi = (const float*)d_in[10];
    const float* bf = (const float*)d_in[11];
    const float* bo = (const float*)d_in[12];
    float* out = (float*)d_out;

    static bool attr_set = false;
    if (!attr_set) {
        cudaFuncSetAttribute(lstm_rec_tc, cudaFuncAttributeMaxDynamicSharedMemorySize,
                             SMEM_RTC);
        attr_set = true;
    }

    zero_init<<<128, 256>>>();
    build_abf<<<(B_ * T_ * D_) / 256, 256>>>(x);
    build_bbf<<<(4 * D_ * H_) / 256, 256>>>(Wc, Wi, Wf, Wo);
    {
        dim3 ug(16, 16, 4);
        build_ubf<<<ug, 256>>>(Uc, Ui, Uf, Uo);
    }

    dim3 ggrid(2048 / 128, (B_ * T_) / 128);   // (16, 256)
    gemm_tc<<<ggrid, 256>>>(bc, bi, bf, bo);

    lstm_rec_tc<<<128, 256, SMEM_RTC>>>(out);
}